// round 13
// baseline (speedup 1.0000x reference)
#include <cuda_runtime.h>
#include <cstdint>

// VoxelBracketPredictor_v2 — ONE fused kernel (R8 + in-kernel bounds + depth-4
// cp.async ring + float4 consume):
//  CTA = 8 CONTIGUOUS samples, 256 threads, 4 CTAs/SM (52.3KB dynamic smem).
//  - segment bounds: warp-cooperative 32-ary lower_bound (no bounds kernel)
//  - pool: cp.async ring, DEPTH 4 (per-warp BW is RTT-bound: BW = depth*1536/RTT),
//          consume via 3x LDS.128 per chunk
//  - coarse MLP: CTA-cooperative; refinement warp-per-sample (R8 layout)

#define EPS 1e-5f
#define RING_FLOATS (4 * 384)            // 4 bufs x 4 rows x 96 ch
#define SMEM_FLOATS (8 * RING_FLOATS + 8 * 96 + 16)

__device__ __forceinline__ float warpSum(float v) {
#pragma unroll
    for (int o = 16; o; o >>= 1) v += __shfl_xor_sync(0xffffffffu, v, o);
    return v;
}

// warp-cooperative lower_bound: first idx with seg[idx] >= v over sorted seg[0..N)
__device__ __forceinline__ int lb32(const int* __restrict__ seg, int N, int v, int lane) {
    int lo = 0, hi = N;
    while (hi - lo > 32) {
        const int span = hi - lo;
        const int pos = lo + (int)(((long long)span * lane) >> 5);
        const int val = seg[pos];
        const unsigned m = __ballot_sync(0xffffffffu, val < v);
        if (m == 0) return lo;
        const int j = 31 - __clz(m);
        const int pos_j  = __shfl_sync(0xffffffffu, pos, j);
        const int pos_j1 = (j < 31) ? __shfl_sync(0xffffffffu, pos, j + 1) : hi;
        lo = pos_j + 1;
        hi = pos_j1;
    }
    const int pos = lo + lane;
    const int val = (pos < hi) ? seg[pos] : 0x7fffffff;
    const unsigned m = __ballot_sync(0xffffffffu, (pos < hi) && (val < v));
    return lo + __popc(m);
}

__device__ __forceinline__ uint32_t smem_u32(const void* p) {
    uint32_t a;
    asm("{ .reg .u64 t; cvta.to.shared.u64 t, %1; cvt.u32.u64 %0, t; }" : "=r"(a) : "l"(p));
    return a;
}
__device__ __forceinline__ void cp_async16(uint32_t saddr, const void* gaddr) {
    asm volatile("cp.async.cg.shared.global [%0], [%1], 16;" :: "r"(saddr), "l"(gaddr));
}
#define CP_COMMIT() asm volatile("cp.async.commit_group;" ::)
#define CP_WAIT(n)  asm volatile("cp.async.wait_group %0;" :: "n"(n))

__global__ __launch_bounds__(256) void fused_kernel(
    const float* __restrict__ feat, const int* __restrict__ seg,
    const int* __restrict__ cls,
    const float* __restrict__ cW1, const float* __restrict__ cb1,
    const float* __restrict__ cg1, const float* __restrict__ cbe1,
    const float* __restrict__ cW2, const float* __restrict__ cb2,
    const float* __restrict__ cg2, const float* __restrict__ cbe2,
    const float* __restrict__ cW3, const float* __restrict__ cb3,
    const float* __restrict__ rW1, const float* __restrict__ rb1,
    const float* __restrict__ rg1, const float* __restrict__ rbe1,
    const float* __restrict__ rW2, const float* __restrict__ rb2,
    const float* __restrict__ rg2, const float* __restrict__ rbe2,
    const float* __restrict__ rW3, const float* __restrict__ rb3,
    float* __restrict__ out, int N, int B)
{
    extern __shared__ float dynsmem[];
    float* smem_all = dynsmem;                       // rings (8 x RING_FLOATS) / MLP acts
    float (*sin_)[96] = reinterpret_cast<float(*)[96]>(dynsmem + 8 * RING_FLOATS);
    float (*sstat)[2] = reinterpret_cast<float(*)[2]>(dynsmem + 8 * RING_FLOATS + 768);
    __shared__ int sbound[9];

    const int tid = threadIdx.x, lane = tid & 31, w = tid >> 5;
    const int b8 = blockIdx.x * 8;
    const int b = b8 + w;
    const bool valid = b < B;
    const int bc = valid ? b : B - 1;

    // ============ phase 0: segment bounds via warp 32-ary search ============
    {
        int s = lb32(seg, N, min(b8 + w, B), lane);
        if (lane == 0) sbound[w] = s;
        if (w == 0) {
            int s8 = lb32(seg, N, min(b8 + 8, B), lane);
            if (lane == 0) sbound[8] = s8;
        }
    }
    __syncthreads();

    // ================= phase 1: cp.async mean pool (warp per sample) ========
    {
        const int st = sbound[min(bc - b8, 7)];
        const int en = sbound[min(bc - b8, 7) + 1];
        const int nr = en - st;
        const float* gsrc = feat + (size_t)st * 96;
        float* sb = smem_all + w * RING_FLOATS;      // 4 bufs x 384 floats
        const uint32_t sb_u = smem_u32(sb);

        const int T = (nr + 3) >> 2;                 // 4-row chunks
        float4 a0 = make_float4(0.f, 0.f, 0.f, 0.f), a1 = a0, a2 = a0;

        #define ISSUE(i)                                                              \
        {                                                                             \
            const int _i = (i);                                                       \
            const int _cnt = min(4, nr - _i * 4) * 24;                                \
            const uint32_t _sbase = sb_u + (uint32_t)(_i & 3) * 1536u;                \
            const float* _g = gsrc + (size_t)_i * 384;                                \
            if (lane < _cnt)      cp_async16(_sbase + lane * 16u,        _g + lane * 4);        \
            if (lane + 32 < _cnt) cp_async16(_sbase + (lane + 32) * 16u, _g + (lane + 32) * 4); \
            if (lane + 64 < _cnt) cp_async16(_sbase + (lane + 64) * 16u, _g + (lane + 64) * 4); \
            CP_COMMIT();                                                              \
        }

        if (T > 0) ISSUE(0);
        if (T > 1) ISSUE(1);
        if (T > 2) ISSUE(2);
        if (T > 3) ISSUE(3);

        for (int i = 0; i < T; i++) {
            const int after = T - 1 - i;
            if (after >= 3)      CP_WAIT(3);
            else if (after == 2) CP_WAIT(2);
            else if (after == 1) CP_WAIT(1);
            else                 CP_WAIT(0);
            __syncwarp();

            const float4* bp4 = (const float4*)(sb + (i & 3) * 384);
            const int cnt = min(4, nr - i * 4) * 24;   // float4 slots in this chunk
            if (cnt == 96) {
                float4 v0 = bp4[lane], v1 = bp4[lane + 32], v2 = bp4[lane + 64];
                a0.x += v0.x; a0.y += v0.y; a0.z += v0.z; a0.w += v0.w;
                a1.x += v1.x; a1.y += v1.y; a1.z += v1.z; a1.w += v1.w;
                a2.x += v2.x; a2.y += v2.y; a2.z += v2.z; a2.w += v2.w;
            } else {
                if (lane < cnt) {
                    float4 v = bp4[lane];
                    a0.x += v.x; a0.y += v.y; a0.z += v.z; a0.w += v.w;
                }
                if (lane + 32 < cnt) {
                    float4 v = bp4[lane + 32];
                    a1.x += v.x; a1.y += v.y; a1.z += v.z; a1.w += v.w;
                }
                if (lane + 64 < cnt) {
                    float4 v = bp4[lane + 64];
                    a2.x += v.x; a2.y += v.y; a2.z += v.z; a2.w += v.w;
                }
            }
            __syncwarp();
            if (i + 4 < T) ISSUE(i + 4);
        }
        #undef ISSUE

        // combine: write accumulators back into the warp's ring (as [4 rowpos][96 ch])
        __syncwarp();
        float4* sp4 = (float4*)sb;
        sp4[lane]      = a0;
        sp4[lane + 32] = a1;
        sp4[lane + 64] = a2;
        __syncwarp();
        const float inv = 1.f / fmaxf((float)nr, 1.f);
#pragma unroll
        for (int j = 0; j < 3; j++) {
            int c = lane + 32 * j;
            float s = sb[c] + sb[96 + c] + sb[192 + c] + sb[288 + c];
            sin_[w][c] = s * inv;
        }
    }
    __syncthreads();

    float* actA = smem_all;          // 8 x 256
    float* actB = smem_all + 2048;   // 8 x 128
    #define ACTA(s, f) actA[(s) * 256 + (f)]
    #define ACTB(s, f) actB[(s) * 128 + (f)]

    // ================= phase 2: coarse L1 (96 -> 256), CTA-cooperative =====
    float acc[8];
    {
        const int f = tid;
        const float bv = cb1[f];
#pragma unroll
        for (int s = 0; s < 8; s++) acc[s] = bv;
#pragma unroll 2
        for (int c = 0; c < 96; c += 4) {
            float w0 = cW1[(c + 0) * 256 + f];
            float w1 = cW1[(c + 1) * 256 + f];
            float w2 = cW1[(c + 2) * 256 + f];
            float w3 = cW1[(c + 3) * 256 + f];
#pragma unroll
            for (int s = 0; s < 8; s++) {
                float4 x = *(const float4*)(&sin_[s][c]);
                acc[s] = fmaf(x.x, w0, acc[s]);
                acc[s] = fmaf(x.y, w1, acc[s]);
                acc[s] = fmaf(x.z, w2, acc[s]);
                acc[s] = fmaf(x.w, w3, acc[s]);
            }
        }
#pragma unroll
        for (int s = 0; s < 8; s++) ACTA(s, f) = acc[s];
    }
    __syncthreads();
    {   // stats for sample w over 256 features
        float sum = 0.f, sq = 0.f;
#pragma unroll
        for (int j = 0; j < 8; j++) {
            float x = ACTA(w, lane + 32 * j);
            sum += x; sq = fmaf(x, x, sq);
        }
        sum = warpSum(sum); sq = warpSum(sq);
        if (lane == 0) {
            float m = sum * (1.f / 256.f);
            float v = sq * (1.f / 256.f) - m * m;
            sstat[w][0] = m; sstat[w][1] = rsqrtf(v + EPS);
        }
    }
    __syncthreads();
    {
        const int f = tid;
        const float g = cg1[f], e = cbe1[f];
#pragma unroll
        for (int s = 0; s < 8; s++) {
            float m = sstat[s][0], r = sstat[s][1];
            ACTA(s, f) = fmaxf(fmaf((acc[s] - m) * r, g, e), 0.f);
        }
    }
    __syncthreads();

    // ================= phase 3: coarse L2 (256 -> 128), CTA-cooperative ====
    float acc2[4];
    const int fL2 = tid & 127, sh = tid >> 7;
    {
        const float bv = cb2[fL2];
#pragma unroll
        for (int i = 0; i < 4; i++) acc2[i] = bv;
#pragma unroll 2
        for (int c = 0; c < 256; c += 4) {
            float w0 = cW2[(c + 0) * 128 + fL2];
            float w1 = cW2[(c + 1) * 128 + fL2];
            float w2 = cW2[(c + 2) * 128 + fL2];
            float w3 = cW2[(c + 3) * 128 + fL2];
#pragma unroll
            for (int i = 0; i < 4; i++) {
                float4 x = *(const float4*)(&ACTA(sh * 4 + i, c));
                acc2[i] = fmaf(x.x, w0, acc2[i]);
                acc2[i] = fmaf(x.y, w1, acc2[i]);
                acc2[i] = fmaf(x.z, w2, acc2[i]);
                acc2[i] = fmaf(x.w, w3, acc2[i]);
            }
        }
#pragma unroll
        for (int i = 0; i < 4; i++) ACTB(sh * 4 + i, fL2) = acc2[i];
    }
    __syncthreads();
    {   // stats for sample w over 128 features
        float sum = 0.f, sq = 0.f;
#pragma unroll
        for (int j = 0; j < 4; j++) {
            float x = ACTB(w, lane + 32 * j);
            sum += x; sq = fmaf(x, x, sq);
        }
        sum = warpSum(sum); sq = warpSum(sq);
        if (lane == 0) {
            float m = sum * (1.f / 128.f);
            float v = sq * (1.f / 128.f) - m * m;
            sstat[w][0] = m; sstat[w][1] = rsqrtf(v + EPS);
        }
    }
    __syncthreads();
    {
        const float g = cg2[fL2], e = cbe2[fL2];
#pragma unroll
        for (int i = 0; i < 4; i++) {
            int s = sh * 4 + i;
            float m = sstat[s][0], r = sstat[s][1];
            ACTB(s, fL2) = fmaxf(fmaf((acc2[i] - m) * r, g, e), 0.f);
        }
    }
    __syncthreads();

    // ================= phase 4: warp-per-sample — coarse L3 + refinement ===
    float p0 = 0.f, p1 = 0.f, p2 = 0.f;
#pragma unroll
    for (int t = 0; t < 4; t++) {
        int c = lane + 32 * t;
        float x = ACTB(w, c);
        p0 = fmaf(x, cW3[c * 3 + 0], p0);
        p1 = fmaf(x, cW3[c * 3 + 1], p1);
        p2 = fmaf(x, cW3[c * 3 + 2], p2);
    }
    p0 = warpSum(p0) + cb3[0];
    p1 = warpSum(p1) + cb3[1];
    p2 = warpSum(p2) + cb3[2];

    const int k = cls[bc];
    const int f4 = lane * 4, f2 = lane * 2;

    // refine L1: 96 -> 128, LN, ReLU
    {
        const float* W = rW1 + k * 96 * 128;
        float4 bb = *(const float4*)(rb1 + k * 128 + f4);
        float B0[4] = {bb.x, bb.y, bb.z, bb.w};
#pragma unroll 2
        for (int c = 0; c < 96; c += 4) {
            float4 x = *(const float4*)(&sin_[w][c]);
            float4 wv;
            wv = *(const float4*)(W + (c + 0) * 128 + f4);
            B0[0] = fmaf(x.x, wv.x, B0[0]); B0[1] = fmaf(x.x, wv.y, B0[1]);
            B0[2] = fmaf(x.x, wv.z, B0[2]); B0[3] = fmaf(x.x, wv.w, B0[3]);
            wv = *(const float4*)(W + (c + 1) * 128 + f4);
            B0[0] = fmaf(x.y, wv.x, B0[0]); B0[1] = fmaf(x.y, wv.y, B0[1]);
            B0[2] = fmaf(x.y, wv.z, B0[2]); B0[3] = fmaf(x.y, wv.w, B0[3]);
            wv = *(const float4*)(W + (c + 2) * 128 + f4);
            B0[0] = fmaf(x.z, wv.x, B0[0]); B0[1] = fmaf(x.z, wv.y, B0[1]);
            B0[2] = fmaf(x.z, wv.z, B0[2]); B0[3] = fmaf(x.z, wv.w, B0[3]);
            wv = *(const float4*)(W + (c + 3) * 128 + f4);
            B0[0] = fmaf(x.w, wv.x, B0[0]); B0[1] = fmaf(x.w, wv.y, B0[1]);
            B0[2] = fmaf(x.w, wv.z, B0[2]); B0[3] = fmaf(x.w, wv.w, B0[3]);
        }
        float m = warpSum(B0[0] + B0[1] + B0[2] + B0[3]) * (1.f / 128.f);
        float v = 0.f;
#pragma unroll
        for (int j = 0; j < 4; j++) { float d = B0[j] - m; v = fmaf(d, d, v); }
        float r = rsqrtf(warpSum(v) * (1.f / 128.f) + EPS);
        float4 g = *(const float4*)(rg1 + k * 128 + f4);
        float4 e = *(const float4*)(rbe1 + k * 128 + f4);
        float4 o;
        o.x = fmaxf(fmaf((B0[0] - m) * r, g.x, e.x), 0.f);
        o.y = fmaxf(fmaf((B0[1] - m) * r, g.y, e.y), 0.f);
        o.z = fmaxf(fmaf((B0[2] - m) * r, g.z, e.z), 0.f);
        o.w = fmaxf(fmaf((B0[3] - m) * r, g.w, e.w), 0.f);
        *(float4*)(&ACTA(w, f4)) = o;
    }
    __syncwarp();

    // refine L2: 128 -> 64, LN, ReLU
    float r2out0, r2out1;
    {
        const float* W = rW2 + k * 128 * 64;
        float2 bb = *(const float2*)(rb2 + k * 64 + f2);
        float D0[2] = {bb.x, bb.y};
#pragma unroll 2
        for (int c = 0; c < 128; c += 4) {
            float4 x = *(const float4*)(&ACTA(w, c));
            float2 wv;
            wv = *(const float2*)(W + (c + 0) * 64 + f2);
            D0[0] = fmaf(x.x, wv.x, D0[0]); D0[1] = fmaf(x.x, wv.y, D0[1]);
            wv = *(const float2*)(W + (c + 1) * 64 + f2);
            D0[0] = fmaf(x.y, wv.x, D0[0]); D0[1] = fmaf(x.y, wv.y, D0[1]);
            wv = *(const float2*)(W + (c + 2) * 64 + f2);
            D0[0] = fmaf(x.z, wv.x, D0[0]); D0[1] = fmaf(x.z, wv.y, D0[1]);
            wv = *(const float2*)(W + (c + 3) * 64 + f2);
            D0[0] = fmaf(x.w, wv.x, D0[0]); D0[1] = fmaf(x.w, wv.y, D0[1]);
        }
        float m = warpSum(D0[0] + D0[1]) * (1.f / 64.f);
        float d0 = D0[0] - m, d1 = D0[1] - m;
        float r = rsqrtf(warpSum(d0 * d0 + d1 * d1) * (1.f / 64.f) + EPS);
        float2 g = *(const float2*)(rg2 + k * 64 + f2);
        float2 e = *(const float2*)(rbe2 + k * 64 + f2);
        r2out0 = fmaxf(fmaf(d0 * r, g.x, e.x), 0.f);
        r2out1 = fmaxf(fmaf(d1 * r, g.y, e.y), 0.f);
    }
    __syncwarp();

    // refine L3: 64 -> 3 via shuffles (activations stay in regs)
    {
        const float* W3 = rW3 + k * 192;
        float q0 = r2out0 * W3[f2 * 3 + 0] + r2out1 * W3[(f2 + 1) * 3 + 0];
        float q1 = r2out0 * W3[f2 * 3 + 1] + r2out1 * W3[(f2 + 1) * 3 + 1];
        float q2 = r2out0 * W3[f2 * 3 + 2] + r2out1 * W3[(f2 + 1) * 3 + 2];
        q0 = warpSum(q0) + rb3[k * 3 + 0];
        q1 = warpSum(q1) + rb3[k * 3 + 1];
        q2 = warpSum(q2) + rb3[k * 3 + 2];

        if (valid && lane < 3) {
            float pc = (lane == 0) ? p0 : (lane == 1) ? p1 : p2;
            float qc = (lane == 0) ? q0 : (lane == 1) ? q1 : q2;
            out[b * 3 + lane] = pc + qc;
        }
    }
    #undef ACTA
    #undef ACTB
}

// ---------------- launch ----------------
extern "C" void kernel_launch(void* const* d_in, const int* in_sizes, int n_in,
                              void* d_out, int out_size) {
    const float* feat = (const float*)d_in[0];
    const int*   seg  = (const int*)d_in[1];
    const int*   cls  = (const int*)d_in[2];
    const int N = in_sizes[1];
    const int B = in_sizes[2];

    const int smem_bytes = SMEM_FLOATS * 4;   // ~52.3 KB -> 4 CTAs/SM
    cudaFuncSetAttribute(fused_kernel, cudaFuncAttributeMaxDynamicSharedMemorySize,
                         smem_bytes);

    fused_kernel<<<(B + 7) / 8, 256, smem_bytes>>>(
        feat, seg, cls,
        (const float*)d_in[3],  (const float*)d_in[4],  (const float*)d_in[5],  (const float*)d_in[6],
        (const float*)d_in[7],  (const float*)d_in[8],  (const float*)d_in[9],  (const float*)d_in[10],
        (const float*)d_in[11], (const float*)d_in[12],
        (const float*)d_in[13], (const float*)d_in[14], (const float*)d_in[15], (const float*)d_in[16],
        (const float*)d_in[17], (const float*)d_in[18], (const float*)d_in[19], (const float*)d_in[20],
        (const float*)d_in[21], (const float*)d_in[22],
        (float*)d_out, N, B);
}

// round 14
// speedup vs baseline: 1.1574x; 1.1574x over previous
#include <cuda_runtime.h>
#include <cstdint>

// VoxelBracketPredictor_v2 — ONE fused kernel:
//  R8 pool (cp.async depth-3 ring, warp/sample, static smem) + in-kernel lb32
//  segment search + packed fma.rn.f32x2 (FFMA2) in all matmul inner loops.
//  CTA = 8 CONTIGUOUS samples, 256 threads, grid B/8 (one wave).

#define EPS 1e-5f

typedef unsigned long long ull;

__device__ __forceinline__ float warpSum(float v) {
#pragma unroll
    for (int o = 16; o; o >>= 1) v += __shfl_xor_sync(0xffffffffu, v, o);
    return v;
}

// ---- f32x2 packed helpers ----
__device__ __forceinline__ ull pk2(float lo, float hi) {
    ull r;
    asm("mov.b64 %0, {%1, %2};" : "=l"(r) : "r"(__float_as_uint(lo)), "r"(__float_as_uint(hi)));
    return r;
}
__device__ __forceinline__ void fma2(ull& acc, ull a, ull b) {
    asm("fma.rn.f32x2 %0, %1, %2, %3;" : "=l"(acc) : "l"(a), "l"(b), "l"(acc));
}
__device__ __forceinline__ float2 up2(ull v) {
    unsigned lo, hi;
    asm("mov.b64 {%0, %1}, %2;" : "=r"(lo), "=r"(hi) : "l"(v));
    return make_float2(__uint_as_float(lo), __uint_as_float(hi));
}

// warp-cooperative lower_bound: first idx with seg[idx] >= v over sorted seg[0..N)
__device__ __forceinline__ int lb32(const int* __restrict__ seg, int N, int v, int lane) {
    int lo = 0, hi = N;
    while (hi - lo > 32) {
        const int span = hi - lo;
        const int pos = lo + (int)(((long long)span * lane) >> 5);
        const int val = seg[pos];
        const unsigned m = __ballot_sync(0xffffffffu, val < v);
        if (m == 0) return lo;
        const int j = 31 - __clz(m);
        const int pos_j  = __shfl_sync(0xffffffffu, pos, j);
        const int pos_j1 = (j < 31) ? __shfl_sync(0xffffffffu, pos, j + 1) : hi;
        lo = pos_j + 1;
        hi = pos_j1;
    }
    const int pos = lo + lane;
    const int val = (pos < hi) ? seg[pos] : 0x7fffffff;
    const unsigned m = __ballot_sync(0xffffffffu, (pos < hi) && (val < v));
    return lo + __popc(m);
}

__device__ __forceinline__ uint32_t smem_u32(const void* p) {
    uint32_t a;
    asm("{ .reg .u64 t; cvta.to.shared.u64 t, %1; cvt.u32.u64 %0, t; }" : "=r"(a) : "l"(p));
    return a;
}
__device__ __forceinline__ void cp_async16(uint32_t saddr, const void* gaddr) {
    asm volatile("cp.async.cg.shared.global [%0], [%1], 16;" :: "r"(saddr), "l"(gaddr));
}
#define CP_COMMIT() asm volatile("cp.async.commit_group;" ::)
#define CP_WAIT(n)  asm volatile("cp.async.wait_group %0;" :: "n"(n))

__global__ __launch_bounds__(256) void fused_kernel(
    const float* __restrict__ feat, const int* __restrict__ seg,
    const int* __restrict__ cls,
    const float* __restrict__ cW1, const float* __restrict__ cb1,
    const float* __restrict__ cg1, const float* __restrict__ cbe1,
    const float* __restrict__ cW2, const float* __restrict__ cb2,
    const float* __restrict__ cg2, const float* __restrict__ cbe2,
    const float* __restrict__ cW3, const float* __restrict__ cb3,
    const float* __restrict__ rW1, const float* __restrict__ rb1,
    const float* __restrict__ rg1, const float* __restrict__ rbe1,
    const float* __restrict__ rW2, const float* __restrict__ rb2,
    const float* __restrict__ rg2, const float* __restrict__ rbe2,
    const float* __restrict__ rW3, const float* __restrict__ rb3,
    float* __restrict__ out, int N, int B)
{
    __shared__ float smem_all[9216];   // pool ring (8w x 3 x 384) / MLP acts
    __shared__ float sin_[8][96];      // pooled inputs
    __shared__ float sstat[8][2];
    __shared__ int   sbound[9];

    const int tid = threadIdx.x, lane = tid & 31, w = tid >> 5;
    const int b8 = blockIdx.x * 8;
    const int b = b8 + w;
    const bool valid = b < B;
    const int bc = valid ? b : B - 1;

    // ============ phase 0: segment bounds via warp 32-ary search ============
    {
        int s = lb32(seg, N, min(b8 + w, B), lane);
        if (lane == 0) sbound[w] = s;
        if (w == 0) {
            int s8 = lb32(seg, N, min(b8 + 8, B), lane);
            if (lane == 0) sbound[8] = s8;
        }
    }
    __syncthreads();

    // ================= phase 1: cp.async mean pool (warp per sample) ========
    {
        const int widx = min(bc - b8, 7);
        const int st = sbound[widx];
        const int en = sbound[widx + 1];
        const int nr = en - st;
        const float* gsrc = feat + (size_t)st * 96;
        float* sb = smem_all + w * 1152;             // 3 bufs x 384 floats
        const uint32_t sb_u = smem_u32(sb);

        const int T = (nr + 3) >> 2;                 // 4-row chunks
        float a0 = 0.f, a1 = 0.f, a2 = 0.f;

        #define ISSUE(i)                                                              \
        {                                                                             \
            const int _i = (i);                                                       \
            const int _cnt = min(4, nr - _i * 4) * 24;                                \
            const uint32_t _sbase = sb_u + (uint32_t)(_i % 3) * 1536u;                \
            const float* _g = gsrc + (size_t)_i * 384;                                \
            if (lane < _cnt)      cp_async16(_sbase + lane * 16u,        _g + lane * 4);        \
            if (lane + 32 < _cnt) cp_async16(_sbase + (lane + 32) * 16u, _g + (lane + 32) * 4); \
            if (lane + 64 < _cnt) cp_async16(_sbase + (lane + 64) * 16u, _g + (lane + 64) * 4); \
            CP_COMMIT();                                                              \
        }

        if (T > 0) ISSUE(0);
        if (T > 1) ISSUE(1);
        if (T > 2) ISSUE(2);

        for (int i = 0; i < T; i++) {
            const int after = T - 1 - i;
            if (after >= 2)      CP_WAIT(2);
            else if (after == 1) CP_WAIT(1);
            else                 CP_WAIT(0);
            __syncwarp();

            const float* bp = sb + (i % 3) * 384;
            const int rows = min(4, nr - i * 4);
            if (rows == 4) {
#pragma unroll
                for (int r = 0; r < 4; r++) {
                    a0 += bp[r * 96 + lane];
                    a1 += bp[r * 96 + 32 + lane];
                    a2 += bp[r * 96 + 64 + lane];
                }
            } else {
                for (int r = 0; r < rows; r++) {
                    a0 += bp[r * 96 + lane];
                    a1 += bp[r * 96 + 32 + lane];
                    a2 += bp[r * 96 + 64 + lane];
                }
            }
            __syncwarp();
            if (i + 3 < T) ISSUE(i + 3);
        }
        #undef ISSUE

        const float inv = 1.f / fmaxf((float)nr, 1.f);
        sin_[w][lane]      = a0 * inv;
        sin_[w][lane + 32] = a1 * inv;
        sin_[w][lane + 64] = a2 * inv;
    }
    __syncthreads();

    float* actA = smem_all;          // 8 x 256
    float* actB = smem_all + 2048;   // 8 x 128
    #define ACTA(s, f) actA[(s) * 256 + (f)]
    #define ACTB(s, f) actB[(s) * 128 + (f)]

    // ================= phase 2: coarse L1 (96 -> 256), FFMA2 ===============
    float acc[8];
    {
        const int f = tid;
        const float bv = cb1[f];
        ull a2p[8];
#pragma unroll
        for (int s = 0; s < 8; s++) a2p[s] = pk2(bv, 0.f);
#pragma unroll 2
        for (int c = 0; c < 96; c += 4) {
            float w0 = cW1[(c + 0) * 256 + f];
            float w1 = cW1[(c + 1) * 256 + f];
            float w2 = cW1[(c + 2) * 256 + f];
            float w3 = cW1[(c + 3) * 256 + f];
            ull w01 = pk2(w0, w1), w23 = pk2(w2, w3);
#pragma unroll
            for (int s = 0; s < 8; s++) {
                ulonglong2 x = *(const ulonglong2*)(&sin_[s][c]);
                fma2(a2p[s], x.x, w01);
                fma2(a2p[s], x.y, w23);
            }
        }
#pragma unroll
        for (int s = 0; s < 8; s++) {
            float2 p = up2(a2p[s]);
            acc[s] = p.x + p.y;
            ACTA(s, f) = acc[s];
        }
    }
    __syncthreads();
    {   // LN stats over 256 (warp w -> sample w)
        float sum = 0.f, sq = 0.f;
#pragma unroll
        for (int j = 0; j < 8; j++) {
            float x = ACTA(w, lane + 32 * j);
            sum += x; sq = fmaf(x, x, sq);
        }
        sum = warpSum(sum); sq = warpSum(sq);
        if (lane == 0) {
            float m = sum * (1.f / 256.f);
            float v = sq * (1.f / 256.f) - m * m;
            sstat[w][0] = m; sstat[w][1] = rsqrtf(v + EPS);
        }
    }
    __syncthreads();
    {
        const int f = tid;
        const float g = cg1[f], e = cbe1[f];
#pragma unroll
        for (int s = 0; s < 8; s++) {
            float m = sstat[s][0], r = sstat[s][1];
            ACTA(s, f) = fmaxf(fmaf((acc[s] - m) * r, g, e), 0.f);
        }
    }
    __syncthreads();

    // ================= phase 3: coarse L2 (256 -> 128), FFMA2 ==============
    float acc2[4];
    const int fL2 = tid & 127, sh = tid >> 7;
    {
        const float bv = cb2[fL2];
        ull a2p[4];
#pragma unroll
        for (int i = 0; i < 4; i++) a2p[i] = pk2(bv, 0.f);
#pragma unroll 2
        for (int c = 0; c < 256; c += 4) {
            float w0 = cW2[(c + 0) * 128 + fL2];
            float w1 = cW2[(c + 1) * 128 + fL2];
            float w2 = cW2[(c + 2) * 128 + fL2];
            float w3 = cW2[(c + 3) * 128 + fL2];
            ull w01 = pk2(w0, w1), w23 = pk2(w2, w3);
#pragma unroll
            for (int i = 0; i < 4; i++) {
                ulonglong2 x = *(const ulonglong2*)(&ACTA(sh * 4 + i, c));
                fma2(a2p[i], x.x, w01);
                fma2(a2p[i], x.y, w23);
            }
        }
#pragma unroll
        for (int i = 0; i < 4; i++) {
            float2 p = up2(a2p[i]);
            acc2[i] = p.x + p.y;
            ACTB(sh * 4 + i, fL2) = acc2[i];
        }
    }
    __syncthreads();
    {   // LN stats over 128
        float sum = 0.f, sq = 0.f;
#pragma unroll
        for (int j = 0; j < 4; j++) {
            float x = ACTB(w, lane + 32 * j);
            sum += x; sq = fmaf(x, x, sq);
        }
        sum = warpSum(sum); sq = warpSum(sq);
        if (lane == 0) {
            float m = sum * (1.f / 128.f);
            float v = sq * (1.f / 128.f) - m * m;
            sstat[w][0] = m; sstat[w][1] = rsqrtf(v + EPS);
        }
    }
    __syncthreads();
    {
        const float g = cg2[fL2], e = cbe2[fL2];
#pragma unroll
        for (int i = 0; i < 4; i++) {
            int s = sh * 4 + i;
            float m = sstat[s][0], r = sstat[s][1];
            ACTB(s, fL2) = fmaxf(fmaf((acc2[i] - m) * r, g, e), 0.f);
        }
    }
    __syncthreads();

    // ================= phase 4: warp-per-sample — coarse L3 + refinement ===
    float p0 = 0.f, p1 = 0.f, p2 = 0.f;
#pragma unroll
    for (int t = 0; t < 4; t++) {
        int c = lane + 32 * t;
        float x = ACTB(w, c);
        p0 = fmaf(x, cW3[c * 3 + 0], p0);
        p1 = fmaf(x, cW3[c * 3 + 1], p1);
        p2 = fmaf(x, cW3[c * 3 + 2], p2);
    }
    p0 = warpSum(p0) + cb3[0];
    p1 = warpSum(p1) + cb3[1];
    p2 = warpSum(p2) + cb3[2];

    const int k = cls[bc];
    const int f4 = lane * 4, f2 = lane * 2;

    // refine L1: 96 -> 128, FFMA2, LN, ReLU
    {
        const float* W = rW1 + k * 96 * 128;
        float4 bb = *(const float4*)(rb1 + k * 128 + f4);
        ull B01 = pk2(bb.x, bb.y), B23 = pk2(bb.z, bb.w);
#pragma unroll 2
        for (int c = 0; c < 96; c += 4) {
            float4 x = *(const float4*)(&sin_[w][c]);
            ulonglong2 wv;
            ull xx;
            wv = *(const ulonglong2*)(W + (c + 0) * 128 + f4);
            xx = pk2(x.x, x.x); fma2(B01, xx, wv.x); fma2(B23, xx, wv.y);
            wv = *(const ulonglong2*)(W + (c + 1) * 128 + f4);
            xx = pk2(x.y, x.y); fma2(B01, xx, wv.x); fma2(B23, xx, wv.y);
            wv = *(const ulonglong2*)(W + (c + 2) * 128 + f4);
            xx = pk2(x.z, x.z); fma2(B01, xx, wv.x); fma2(B23, xx, wv.y);
            wv = *(const ulonglong2*)(W + (c + 3) * 128 + f4);
            xx = pk2(x.w, x.w); fma2(B01, xx, wv.x); fma2(B23, xx, wv.y);
        }
        float2 b01 = up2(B01), b23 = up2(B23);
        float B0[4] = {b01.x, b01.y, b23.x, b23.y};
        float m = warpSum(B0[0] + B0[1] + B0[2] + B0[3]) * (1.f / 128.f);
        float v = 0.f;
#pragma unroll
        for (int j = 0; j < 4; j++) { float d = B0[j] - m; v = fmaf(d, d, v); }
        float r = rsqrtf(warpSum(v) * (1.f / 128.f) + EPS);
        float4 g = *(const float4*)(rg1 + k * 128 + f4);
        float4 e = *(const float4*)(rbe1 + k * 128 + f4);
        float4 o;
        o.x = fmaxf(fmaf((B0[0] - m) * r, g.x, e.x), 0.f);
        o.y = fmaxf(fmaf((B0[1] - m) * r, g.y, e.y), 0.f);
        o.z = fmaxf(fmaf((B0[2] - m) * r, g.z, e.z), 0.f);
        o.w = fmaxf(fmaf((B0[3] - m) * r, g.w, e.w), 0.f);
        *(float4*)(&ACTA(w, f4)) = o;
    }
    __syncwarp();

    // refine L2: 128 -> 64, FFMA2, LN, ReLU
    float r2out0, r2out1;
    {
        const float* W = rW2 + k * 128 * 64;
        float2 bb = *(const float2*)(rb2 + k * 64 + f2);
        ull D01 = pk2(bb.x, bb.y);
#pragma unroll 2
        for (int c = 0; c < 128; c += 4) {
            float4 x = *(const float4*)(&ACTA(w, c));
            ull wv, xx;
            wv = *(const ull*)(W + (c + 0) * 64 + f2);
            xx = pk2(x.x, x.x); fma2(D01, xx, wv);
            wv = *(const ull*)(W + (c + 1) * 64 + f2);
            xx = pk2(x.y, x.y); fma2(D01, xx, wv);
            wv = *(const ull*)(W + (c + 2) * 64 + f2);
            xx = pk2(x.z, x.z); fma2(D01, xx, wv);
            wv = *(const ull*)(W + (c + 3) * 64 + f2);
            xx = pk2(x.w, x.w); fma2(D01, xx, wv);
        }
        float2 d01 = up2(D01);
        float m = warpSum(d01.x + d01.y) * (1.f / 64.f);
        float d0 = d01.x - m, d1 = d01.y - m;
        float r = rsqrtf(warpSum(d0 * d0 + d1 * d1) * (1.f / 64.f) + EPS);
        float2 g = *(const float2*)(rg2 + k * 64 + f2);
        float2 e = *(const float2*)(rbe2 + k * 64 + f2);
        r2out0 = fmaxf(fmaf(d0 * r, g.x, e.x), 0.f);
        r2out1 = fmaxf(fmaf(d1 * r, g.y, e.y), 0.f);
    }
    __syncwarp();

    // refine L3: 64 -> 3 via shuffles (activations stay in regs)
    {
        const float* W3 = rW3 + k * 192;
        float q0 = r2out0 * W3[f2 * 3 + 0] + r2out1 * W3[(f2 + 1) * 3 + 0];
        float q1 = r2out0 * W3[f2 * 3 + 1] + r2out1 * W3[(f2 + 1) * 3 + 1];
        float q2 = r2out0 * W3[f2 * 3 + 2] + r2out1 * W3[(f2 + 1) * 3 + 2];
        q0 = warpSum(q0) + rb3[k * 3 + 0];
        q1 = warpSum(q1) + rb3[k * 3 + 1];
        q2 = warpSum(q2) + rb3[k * 3 + 2];

        if (valid && lane < 3) {
            float pc = (lane == 0) ? p0 : (lane == 1) ? p1 : p2;
            float qc = (lane == 0) ? q0 : (lane == 1) ? q1 : q2;
            out[b * 3 + lane] = pc + qc;
        }
    }
    #undef ACTA
    #undef ACTB
}

// ---------------- launch ----------------
extern "C" void kernel_launch(void* const* d_in, const int* in_sizes, int n_in,
                              void* d_out, int out_size) {
    const float* feat = (const float*)d_in[0];
    const int*   seg  = (const int*)d_in[1];
    const int*   cls  = (const int*)d_in[2];
    const int N = in_sizes[1];
    const int B = in_sizes[2];

    fused_kernel<<<(B + 7) / 8, 256>>>(
        feat, seg, cls,
        (const float*)d_in[3],  (const float*)d_in[4],  (const float*)d_in[5],  (const float*)d_in[6],
        (const float*)d_in[7],  (const float*)d_in[8],  (const float*)d_in[9],  (const float*)d_in[10],
        (const float*)d_in[11], (const float*)d_in[12],
        (const float*)d_in[13], (const float*)d_in[14], (const float*)d_in[15], (const float*)d_in[16],
        (const float*)d_in[17], (const float*)d_in[18], (const float*)d_in[19], (const float*)d_in[20],
        (const float*)d_in[21], (const float*)d_in[22],
        (float*)d_out, N, B);
}

// round 15
// speedup vs baseline: 1.1703x; 1.0111x over previous
#include <cuda_runtime.h>
#include <cstdint>

// VoxelBracketPredictor_v2 — 2-kernel pipeline:
//  k0 bounds: segment boundaries (int4 scan; coalesced — measured better than in-kernel search)
//  k1 fused:  CTA = 16 CONTIGUOUS samples, 512 threads (16 warps), grid B/16=256,
//             2 CTAs/SM -> all 4096 pooling warps resident (same pool BW as R8).
//             pool: cp.async depth-3 ring, warp per sample.
//             coarse MLP: CTA-cooperative with C-SPLIT (cW1/cW2 read ONCE per CTA
//             -> coarse weight traffic halved vs 8-sample CTAs).
//             refinement: warp-per-sample (unchanged).

#define EPS 1e-5f
#define BMAX 4096

__device__ int g_bound[BMAX + 1];

// ---------------- kernel 0: boundaries ----------------
__global__ void bounds_kernel(const int* __restrict__ seg, int N, int B) {
    int t = blockIdx.x * blockDim.x + threadIdx.x;
    int i = t * 4;
    if (i >= N) return;
    int vals[4];
    if (i + 4 <= N) {
        int4 v = *(const int4*)(seg + i);
        vals[0] = v.x; vals[1] = v.y; vals[2] = v.z; vals[3] = v.w;
    } else {
        for (int j = 0; j < 4; j++) vals[j] = (i + j < N) ? seg[i + j] : vals[j > 0 ? j - 1 : 0];
    }
    int prev = (i == 0) ? -1 : seg[i - 1];
    int lim = min(4, N - i);
    for (int j = 0; j < lim; j++) {
        int cur = vals[j];
        for (int b = prev + 1; b <= cur; b++) g_bound[b] = i + j;
        prev = cur;
    }
    if (i + 4 >= N)
        for (int b = prev + 1; b <= B; b++) g_bound[b] = N;
}

__device__ __forceinline__ float warpSum(float v) {
#pragma unroll
    for (int o = 16; o; o >>= 1) v += __shfl_xor_sync(0xffffffffu, v, o);
    return v;
}

__device__ __forceinline__ uint32_t smem_u32(const void* p) {
    uint32_t a;
    asm("{ .reg .u64 t; cvta.to.shared.u64 t, %1; cvt.u32.u64 %0, t; }" : "=r"(a) : "l"(p));
    return a;
}
__device__ __forceinline__ void cp_async16(uint32_t saddr, const void* gaddr) {
    asm volatile("cp.async.cg.shared.global [%0], [%1], 16;" :: "r"(saddr), "l"(gaddr));
}
#define CP_COMMIT() asm volatile("cp.async.commit_group;" ::)
#define CP_WAIT(n)  asm volatile("cp.async.wait_group %0;" :: "n"(n))

// dynamic smem layout (floats):
//  [0, 18432)            pool ring: 16 warps x 3 bufs x 384
//    post-pool aliases:  actA = [0,4096)  (16 x 256)
//                        actB = [4096,6144) (16 x 128)
//                        part = [6144,14336) (8192: [2][16][256] or [4][16][128])
//  [18432, 19968)        sin_ : 16 x 96
#define SMEM_FLOATS 19968

__global__ __launch_bounds__(512, 2) void fused_kernel(
    const float* __restrict__ feat, const int* __restrict__ cls,
    const float* __restrict__ cW1, const float* __restrict__ cb1,
    const float* __restrict__ cg1, const float* __restrict__ cbe1,
    const float* __restrict__ cW2, const float* __restrict__ cb2,
    const float* __restrict__ cg2, const float* __restrict__ cbe2,
    const float* __restrict__ cW3, const float* __restrict__ cb3,
    const float* __restrict__ rW1, const float* __restrict__ rb1,
    const float* __restrict__ rg1, const float* __restrict__ rbe1,
    const float* __restrict__ rW2, const float* __restrict__ rb2,
    const float* __restrict__ rg2, const float* __restrict__ rbe2,
    const float* __restrict__ rW3, const float* __restrict__ rb3,
    float* __restrict__ out, int B)
{
    extern __shared__ float dyns[];
    float* ring = dyns;
    float* actA = dyns;                 // 16 x 256
    float* actB = dyns + 4096;          // 16 x 128
    float* part = dyns + 6144;          // 8192
    float (*sin_)[96] = reinterpret_cast<float(*)[96]>(dyns + 18432);
    __shared__ float sstat[16][2];

    const int tid = threadIdx.x, lane = tid & 31, w = tid >> 5;   // w in [0,16)
    const int b16 = blockIdx.x * 16;
    const int b = b16 + w;
    const bool valid = b < B;
    const int bc = valid ? b : B - 1;

    #define ACTA(s, f) actA[(s) * 256 + (f)]
    #define ACTB(s, f) actB[(s) * 128 + (f)]

    // ================= phase 1: cp.async mean pool (warp per sample) ========
    {
        const int st = g_bound[bc], en = g_bound[bc + 1];
        const int nr = en - st;
        const float* gsrc = feat + (size_t)st * 96;
        float* sb = ring + w * 1152;                 // 3 bufs x 384 floats
        const uint32_t sb_u = smem_u32(sb);

        const int T = (nr + 3) >> 2;
        float a0 = 0.f, a1 = 0.f, a2 = 0.f;

        #define ISSUE(i)                                                              \
        {                                                                             \
            const int _i = (i);                                                       \
            const int _cnt = min(4, nr - _i * 4) * 24;                                \
            const uint32_t _sbase = sb_u + (uint32_t)(_i % 3) * 1536u;                \
            const float* _g = gsrc + (size_t)_i * 384;                                \
            if (lane < _cnt)      cp_async16(_sbase + lane * 16u,        _g + lane * 4);        \
            if (lane + 32 < _cnt) cp_async16(_sbase + (lane + 32) * 16u, _g + (lane + 32) * 4); \
            if (lane + 64 < _cnt) cp_async16(_sbase + (lane + 64) * 16u, _g + (lane + 64) * 4); \
            CP_COMMIT();                                                              \
        }

        if (T > 0) ISSUE(0);
        if (T > 1) ISSUE(1);
        if (T > 2) ISSUE(2);

        for (int i = 0; i < T; i++) {
            const int after = T - 1 - i;
            if (after >= 2)      CP_WAIT(2);
            else if (after == 1) CP_WAIT(1);
            else                 CP_WAIT(0);
            __syncwarp();

            const float* bp = sb + (i % 3) * 384;
            const int rows = min(4, nr - i * 4);
            if (rows == 4) {
#pragma unroll
                for (int r = 0; r < 4; r++) {
                    a0 += bp[r * 96 + lane];
                    a1 += bp[r * 96 + 32 + lane];
                    a2 += bp[r * 96 + 64 + lane];
                }
            } else {
                for (int r = 0; r < rows; r++) {
                    a0 += bp[r * 96 + lane];
                    a1 += bp[r * 96 + 32 + lane];
                    a2 += bp[r * 96 + 64 + lane];
                }
            }
            __syncwarp();
            if (i + 3 < T) ISSUE(i + 3);
        }
        #undef ISSUE

        const float inv = 1.f / fmaxf((float)nr, 1.f);
        sin_[w][lane]      = a0 * inv;
        sin_[w][lane + 32] = a1 * inv;
        sin_[w][lane + 64] = a2 * inv;
    }
    __syncthreads();

    // ================= coarse L1 (96 -> 256), c-split (2 halves) ============
    const int f1 = tid & 255, h1 = tid >> 8;       // h1 in {0,1}, c in [h1*48, h1*48+48)
    {
        float acc[16];
        const float bv = (h1 == 0) ? cb1[f1] : 0.f;
#pragma unroll
        for (int s = 0; s < 16; s++) acc[s] = bv;
        const int c0 = h1 * 48;
#pragma unroll 2
        for (int cc = 0; cc < 48; cc += 4) {
            const int c = c0 + cc;
            float w0 = cW1[(c + 0) * 256 + f1];
            float w1 = cW1[(c + 1) * 256 + f1];
            float w2 = cW1[(c + 2) * 256 + f1];
            float w3 = cW1[(c + 3) * 256 + f1];
#pragma unroll
            for (int s = 0; s < 16; s++) {
                float4 x = *(const float4*)(&sin_[s][c]);
                acc[s] = fmaf(x.x, w0, acc[s]);
                acc[s] = fmaf(x.y, w1, acc[s]);
                acc[s] = fmaf(x.z, w2, acc[s]);
                acc[s] = fmaf(x.w, w3, acc[s]);
            }
        }
#pragma unroll
        for (int s = 0; s < 16; s++) part[h1 * 4096 + s * 256 + f1] = acc[s];
    }
    __syncthreads();
    {   // LN stats over 256 (warp w -> sample w), from combined partials
        float sum = 0.f, sq = 0.f;
#pragma unroll
        for (int j = 0; j < 8; j++) {
            int f = lane + 32 * j;
            float x = part[w * 256 + f] + part[4096 + w * 256 + f];
            sum += x; sq = fmaf(x, x, sq);
        }
        sum = warpSum(sum); sq = warpSum(sq);
        if (lane == 0) {
            float m = sum * (1.f / 256.f);
            float v = sq * (1.f / 256.f) - m * m;
            sstat[w][0] = m; sstat[w][1] = rsqrtf(v + EPS);
        }
    }
    __syncthreads();
    {   // combine + LN + ReLU -> ACTA ; thread covers samples s = h1 + 2i
        const float g = cg1[f1], e = cbe1[f1];
#pragma unroll
        for (int i = 0; i < 8; i++) {
            const int s = h1 + 2 * i;
            float x = part[s * 256 + f1] + part[4096 + s * 256 + f1];
            ACTA(s, f1) = fmaxf(fmaf((x - sstat[s][0]) * sstat[s][1], g, e), 0.f);
        }
    }
    __syncthreads();

    // ================= coarse L2 (256 -> 128), c-split (4 quarters) =========
    const int f2q = tid & 127, q2 = tid >> 7;      // q2 in 0..3, c in [q2*64, q2*64+64)
    {
        float acc[16];
        const float bv = (q2 == 0) ? cb2[f2q] : 0.f;
#pragma unroll
        for (int s = 0; s < 16; s++) acc[s] = bv;
        const int c0 = q2 * 64;
#pragma unroll 2
        for (int cc = 0; cc < 64; cc += 4) {
            const int c = c0 + cc;
            float w0 = cW2[(c + 0) * 128 + f2q];
            float w1 = cW2[(c + 1) * 128 + f2q];
            float w2 = cW2[(c + 2) * 128 + f2q];
            float w3 = cW2[(c + 3) * 128 + f2q];
#pragma unroll
            for (int s = 0; s < 16; s++) {
                float4 x = *(const float4*)(&ACTA(s, c));
                acc[s] = fmaf(x.x, w0, acc[s]);
                acc[s] = fmaf(x.y, w1, acc[s]);
                acc[s] = fmaf(x.z, w2, acc[s]);
                acc[s] = fmaf(x.w, w3, acc[s]);
            }
        }
#pragma unroll
        for (int s = 0; s < 16; s++) part[q2 * 2048 + s * 128 + f2q] = acc[s];
    }
    __syncthreads();
    {   // LN stats over 128 (warp w -> sample w)
        float sum = 0.f, sq = 0.f;
#pragma unroll
        for (int j = 0; j < 4; j++) {
            int f = lane + 32 * j;
            float x = part[w * 128 + f] + part[2048 + w * 128 + f]
                    + part[4096 + w * 128 + f] + part[6144 + w * 128 + f];
            sum += x; sq = fmaf(x, x, sq);
        }
        sum = warpSum(sum); sq = warpSum(sq);
        if (lane == 0) {
            float m = sum * (1.f / 128.f);
            float v = sq * (1.f / 128.f) - m * m;
            sstat[w][0] = m; sstat[w][1] = rsqrtf(v + EPS);
        }
    }
    __syncthreads();
    {   // combine + LN + ReLU -> ACTB ; thread covers samples s = q2 + 4i
        const float g = cg2[f2q], e = cbe2[f2q];
#pragma unroll
        for (int i = 0; i < 4; i++) {
            const int s = q2 + 4 * i;
            float x = part[s * 128 + f2q] + part[2048 + s * 128 + f2q]
                    + part[4096 + s * 128 + f2q] + part[6144 + s * 128 + f2q];
            ACTB(s, f2q) = fmaxf(fmaf((x - sstat[s][0]) * sstat[s][1], g, e), 0.f);
        }
    }
    __syncthreads();

    // ================= coarse L3 (warp w -> sample w) =======================
    float p0 = 0.f, p1 = 0.f, p2 = 0.f;
#pragma unroll
    for (int t = 0; t < 4; t++) {
        int c = lane + 32 * t;
        float x = ACTB(w, c);
        p0 = fmaf(x, cW3[c * 3 + 0], p0);
        p1 = fmaf(x, cW3[c * 3 + 1], p1);
        p2 = fmaf(x, cW3[c * 3 + 2], p2);
    }
    p0 = warpSum(p0) + cb3[0];
    p1 = warpSum(p1) + cb3[1];
    p2 = warpSum(p2) + cb3[2];

    const int k = cls[bc];
    const int f4 = lane * 4, f2 = lane * 2;

    // ================= refine L1: 96 -> 128, warp-per-sample ================
    {
        const float* W = rW1 + k * 96 * 128;
        float4 bb = *(const float4*)(rb1 + k * 128 + f4);
        float B0[4] = {bb.x, bb.y, bb.z, bb.w};
#pragma unroll 2
        for (int c = 0; c < 96; c += 4) {
            float4 x = *(const float4*)(&sin_[w][c]);
            float4 wv;
            wv = *(const float4*)(W + (c + 0) * 128 + f4);
            B0[0] = fmaf(x.x, wv.x, B0[0]); B0[1] = fmaf(x.x, wv.y, B0[1]);
            B0[2] = fmaf(x.x, wv.z, B0[2]); B0[3] = fmaf(x.x, wv.w, B0[3]);
            wv = *(const float4*)(W + (c + 1) * 128 + f4);
            B0[0] = fmaf(x.y, wv.x, B0[0]); B0[1] = fmaf(x.y, wv.y, B0[1]);
            B0[2] = fmaf(x.y, wv.z, B0[2]); B0[3] = fmaf(x.y, wv.w, B0[3]);
            wv = *(const float4*)(W + (c + 2) * 128 + f4);
            B0[0] = fmaf(x.z, wv.x, B0[0]); B0[1] = fmaf(x.z, wv.y, B0[1]);
            B0[2] = fmaf(x.z, wv.z, B0[2]); B0[3] = fmaf(x.z, wv.w, B0[3]);
            wv = *(const float4*)(W + (c + 3) * 128 + f4);
            B0[0] = fmaf(x.w, wv.x, B0[0]); B0[1] = fmaf(x.w, wv.y, B0[1]);
            B0[2] = fmaf(x.w, wv.z, B0[2]); B0[3] = fmaf(x.w, wv.w, B0[3]);
        }
        float m = warpSum(B0[0] + B0[1] + B0[2] + B0[3]) * (1.f / 128.f);
        float v = 0.f;
#pragma unroll
        for (int j = 0; j < 4; j++) { float d = B0[j] - m; v = fmaf(d, d, v); }
        float r = rsqrtf(warpSum(v) * (1.f / 128.f) + EPS);
        float4 g = *(const float4*)(rg1 + k * 128 + f4);
        float4 e = *(const float4*)(rbe1 + k * 128 + f4);
        float4 o;
        o.x = fmaxf(fmaf((B0[0] - m) * r, g.x, e.x), 0.f);
        o.y = fmaxf(fmaf((B0[1] - m) * r, g.y, e.y), 0.f);
        o.z = fmaxf(fmaf((B0[2] - m) * r, g.z, e.z), 0.f);
        o.w = fmaxf(fmaf((B0[3] - m) * r, g.w, e.w), 0.f);
        *(float4*)(&ACTA(w, f4)) = o;
    }
    __syncwarp();

    // ================= refine L2: 128 -> 64, warp-per-sample ================
    float r2out0, r2out1;
    {
        const float* W = rW2 + k * 128 * 64;
        float2 bb = *(const float2*)(rb2 + k * 64 + f2);
        float D0[2] = {bb.x, bb.y};
#pragma unroll 2
        for (int c = 0; c < 128; c += 4) {
            float4 x = *(const float4*)(&ACTA(w, c));
            float2 wv;
            wv = *(const float2*)(W + (c + 0) * 64 + f2);
            D0[0] = fmaf(x.x, wv.x, D0[0]); D0[1] = fmaf(x.x, wv.y, D0[1]);
            wv = *(const float2*)(W + (c + 1) * 64 + f2);
            D0[0] = fmaf(x.y, wv.x, D0[0]); D0[1] = fmaf(x.y, wv.y, D0[1]);
            wv = *(const float2*)(W + (c + 2) * 64 + f2);
            D0[0] = fmaf(x.z, wv.x, D0[0]); D0[1] = fmaf(x.z, wv.y, D0[1]);
            wv = *(const float2*)(W + (c + 3) * 64 + f2);
            D0[0] = fmaf(x.w, wv.x, D0[0]); D0[1] = fmaf(x.w, wv.y, D0[1]);
        }
        float m = warpSum(D0[0] + D0[1]) * (1.f / 64.f);
        float d0 = D0[0] - m, d1 = D0[1] - m;
        float r = rsqrtf(warpSum(d0 * d0 + d1 * d1) * (1.f / 64.f) + EPS);
        float2 g = *(const float2*)(rg2 + k * 64 + f2);
        float2 e = *(const float2*)(rbe2 + k * 64 + f2);
        r2out0 = fmaxf(fmaf(d0 * r, g.x, e.x), 0.f);
        r2out1 = fmaxf(fmaf(d1 * r, g.y, e.y), 0.f);
    }
    __syncwarp();

    // ================= refine L3: 64 -> 3 via shuffles, write out ===========
    {
        const float* W3 = rW3 + k * 192;
        float q0 = r2out0 * W3[f2 * 3 + 0] + r2out1 * W3[(f2 + 1) * 3 + 0];
        float q1 = r2out0 * W3[f2 * 3 + 1] + r2out1 * W3[(f2 + 1) * 3 + 1];
        float q2 = r2out0 * W3[f2 * 3 + 2] + r2out1 * W3[(f2 + 1) * 3 + 2];
        q0 = warpSum(q0) + rb3[k * 3 + 0];
        q1 = warpSum(q1) + rb3[k * 3 + 1];
        q2 = warpSum(q2) + rb3[k * 3 + 2];

        if (valid && lane < 3) {
            float pc = (lane == 0) ? p0 : (lane == 1) ? p1 : p2;
            float qc = (lane == 0) ? q0 : (lane == 1) ? q1 : q2;
            out[b * 3 + lane] = pc + qc;
        }
    }
    #undef ACTA
    #undef ACTB
}

// ---------------- launch ----------------
extern "C" void kernel_launch(void* const* d_in, const int* in_sizes, int n_in,
                              void* d_out, int out_size) {
    const float* feat = (const float*)d_in[0];
    const int*   seg  = (const int*)d_in[1];
    const int*   cls  = (const int*)d_in[2];
    const int N = in_sizes[1];
    const int B = in_sizes[2];

    const int smem_bytes = SMEM_FLOATS * 4;       // ~78 KB -> 2 CTAs/SM, 256 CTAs all resident
    cudaFuncSetAttribute(fused_kernel, cudaFuncAttributeMaxDynamicSharedMemorySize,
                         smem_bytes);

    bounds_kernel<<<(N / 4 + 255) / 256, 256>>>(seg, N, B);
    fused_kernel<<<(B + 15) / 16, 512, smem_bytes>>>(
        feat, cls,
        (const float*)d_in[3],  (const float*)d_in[4],  (const float*)d_in[5],  (const float*)d_in[6],
        (const float*)d_in[7],  (const float*)d_in[8],  (const float*)d_in[9],  (const float*)d_in[10],
        (const float*)d_in[11], (const float*)d_in[12],
        (const float*)d_in[13], (const float*)d_in[14], (const float*)d_in[15], (const float*)d_in[16],
        (const float*)d_in[17], (const float*)d_in[18], (const float*)d_in[19], (const float*)d_in[20],
        (const float*)d_in[21], (const float*)d_in[22],
        (float*)d_out, B);
}

// round 16
// speedup vs baseline: 1.2065x; 1.0310x over previous
#include <cuda_runtime.h>
#include <cstdint>

// VoxelBracketPredictor_v2 — 2-kernel pipeline (R15 + class-sorted refine warps):
//  k0 bounds: segment boundaries (int4 scan)
//  k1 fused:  CTA = 16 CONTIGUOUS samples, 512 threads, grid 256, 2 CTAs/SM.
//             pool: cp.async depth-3 ring, warp per sample (contiguous mapping).
//             coarse MLP: CTA-cooperative, c-split (weights read once per CTA).
//             refinement: warp-per-sample but warps are assigned samples SORTED
//             BY CLASS -> same-class warps stream identical weight addresses
//             concurrently (L1/L2 coalescing) with ZERO serialization.

#define EPS 1e-5f
#define BMAX 4096

__device__ int g_bound[BMAX + 1];

// ---------------- kernel 0: boundaries ----------------
__global__ void bounds_kernel(const int* __restrict__ seg, int N, int B) {
    int t = blockIdx.x * blockDim.x + threadIdx.x;
    int i = t * 4;
    if (i >= N) return;
    int vals[4];
    if (i + 4 <= N) {
        int4 v = *(const int4*)(seg + i);
        vals[0] = v.x; vals[1] = v.y; vals[2] = v.z; vals[3] = v.w;
    } else {
        for (int j = 0; j < 4; j++) vals[j] = (i + j < N) ? seg[i + j] : vals[j > 0 ? j - 1 : 0];
    }
    int prev = (i == 0) ? -1 : seg[i - 1];
    int lim = min(4, N - i);
    for (int j = 0; j < lim; j++) {
        int cur = vals[j];
        for (int b = prev + 1; b <= cur; b++) g_bound[b] = i + j;
        prev = cur;
    }
    if (i + 4 >= N)
        for (int b = prev + 1; b <= B; b++) g_bound[b] = N;
}

__device__ __forceinline__ float warpSum(float v) {
#pragma unroll
    for (int o = 16; o; o >>= 1) v += __shfl_xor_sync(0xffffffffu, v, o);
    return v;
}

__device__ __forceinline__ uint32_t smem_u32(const void* p) {
    uint32_t a;
    asm("{ .reg .u64 t; cvta.to.shared.u64 t, %1; cvt.u32.u64 %0, t; }" : "=r"(a) : "l"(p));
    return a;
}
__device__ __forceinline__ void cp_async16(uint32_t saddr, const void* gaddr) {
    asm volatile("cp.async.cg.shared.global [%0], [%1], 16;" :: "r"(saddr), "l"(gaddr));
}
#define CP_COMMIT() asm volatile("cp.async.commit_group;" ::)
#define CP_WAIT(n)  asm volatile("cp.async.wait_group %0;" :: "n"(n))

// dynamic smem layout (floats):
//  [0, 18432)   pool ring: 16 warps x 3 bufs x 384
//    aliases:   actA = [0,4096) (16x256), actB = [4096,6144) (16x128),
//               part = [6144,14336) (8192)
//  [18432, 19968) sin_: 16 x 96
#define SMEM_FLOATS 19968

__global__ __launch_bounds__(512, 2) void fused_kernel(
    const float* __restrict__ feat, const int* __restrict__ cls,
    const float* __restrict__ cW1, const float* __restrict__ cb1,
    const float* __restrict__ cg1, const float* __restrict__ cbe1,
    const float* __restrict__ cW2, const float* __restrict__ cb2,
    const float* __restrict__ cg2, const float* __restrict__ cbe2,
    const float* __restrict__ cW3, const float* __restrict__ cb3,
    const float* __restrict__ rW1, const float* __restrict__ rb1,
    const float* __restrict__ rg1, const float* __restrict__ rbe1,
    const float* __restrict__ rW2, const float* __restrict__ rb2,
    const float* __restrict__ rg2, const float* __restrict__ rbe2,
    const float* __restrict__ rW3, const float* __restrict__ rb3,
    float* __restrict__ out, int B)
{
    extern __shared__ float dyns[];
    float* ring = dyns;
    float* actA = dyns;                 // 16 x 256
    float* actB = dyns + 4096;          // 16 x 128
    float* part = dyns + 6144;          // 8192
    float (*sin_)[96] = reinterpret_cast<float(*)[96]>(dyns + 18432);
    __shared__ float sstat[16][2];
    __shared__ float scoarse[16][3];
    __shared__ int   scls[16];
    __shared__ int   sslot[16];

    const int tid = threadIdx.x, lane = tid & 31, w = tid >> 5;   // w in [0,16)
    const int b16 = blockIdx.x * 16;
    const int b = b16 + w;
    const bool valid = b < B;
    const int bc = valid ? b : B - 1;

    #define ACTA(s, f) actA[(s) * 256 + (f)]
    #define ACTB(s, f) actB[(s) * 128 + (f)]

    if (tid < 16) scls[tid] = cls[min(b16 + tid, B - 1)];

    // ================= phase 1: cp.async mean pool (warp per sample) ========
    {
        const int st = g_bound[bc], en = g_bound[bc + 1];
        const int nr = en - st;
        const float* gsrc = feat + (size_t)st * 96;
        float* sb = ring + w * 1152;                 // 3 bufs x 384 floats
        const uint32_t sb_u = smem_u32(sb);

        const int T = (nr + 3) >> 2;
        float a0 = 0.f, a1 = 0.f, a2 = 0.f;

        #define ISSUE(i)                                                              \
        {                                                                             \
            const int _i = (i);                                                       \
            const int _cnt = min(4, nr - _i * 4) * 24;                                \
            const uint32_t _sbase = sb_u + (uint32_t)(_i % 3) * 1536u;                \
            const float* _g = gsrc + (size_t)_i * 384;                                \
            if (lane < _cnt)      cp_async16(_sbase + lane * 16u,        _g + lane * 4);        \
            if (lane + 32 < _cnt) cp_async16(_sbase + (lane + 32) * 16u, _g + (lane + 32) * 4); \
            if (lane + 64 < _cnt) cp_async16(_sbase + (lane + 64) * 16u, _g + (lane + 64) * 4); \
            CP_COMMIT();                                                              \
        }

        if (T > 0) ISSUE(0);
        if (T > 1) ISSUE(1);
        if (T > 2) ISSUE(2);

        for (int i = 0; i < T; i++) {
            const int after = T - 1 - i;
            if (after >= 2)      CP_WAIT(2);
            else if (after == 1) CP_WAIT(1);
            else                 CP_WAIT(0);
            __syncwarp();

            const float* bp = sb + (i % 3) * 384;
            const int rows = min(4, nr - i * 4);
            if (rows == 4) {
#pragma unroll
                for (int r = 0; r < 4; r++) {
                    a0 += bp[r * 96 + lane];
                    a1 += bp[r * 96 + 32 + lane];
                    a2 += bp[r * 96 + 64 + lane];
                }
            } else {
                for (int r = 0; r < rows; r++) {
                    a0 += bp[r * 96 + lane];
                    a1 += bp[r * 96 + 32 + lane];
                    a2 += bp[r * 96 + 64 + lane];
                }
            }
            __syncwarp();
            if (i + 3 < T) ISSUE(i + 3);
        }
        #undef ISSUE

        const float inv = 1.f / fmaxf((float)nr, 1.f);
        sin_[w][lane]      = a0 * inv;
        sin_[w][lane + 32] = a1 * inv;
        sin_[w][lane + 64] = a2 * inv;
    }
    // class-sort of sample slots (single thread; overlapped with other warps' pooling tails)
    if (tid == 0) {
        int cnt[4] = {0, 0, 0, 0};
        for (int s = 0; s < 16; s++) cnt[scls[s]]++;
        int base[4];
        base[0] = 0;
        for (int kk = 1; kk < 4; kk++) base[kk] = base[kk - 1] + cnt[kk - 1];
        for (int s = 0; s < 16; s++) sslot[base[scls[s]]++] = s;
    }
    __syncthreads();

    // ================= coarse L1 (96 -> 256), c-split (2 halves) ============
    const int f1 = tid & 255, h1 = tid >> 8;
    {
        float acc[16];
        const float bv = (h1 == 0) ? cb1[f1] : 0.f;
#pragma unroll
        for (int s = 0; s < 16; s++) acc[s] = bv;
        const int c0 = h1 * 48;
#pragma unroll 2
        for (int cc = 0; cc < 48; cc += 4) {
            const int c = c0 + cc;
            float w0 = cW1[(c + 0) * 256 + f1];
            float w1 = cW1[(c + 1) * 256 + f1];
            float w2 = cW1[(c + 2) * 256 + f1];
            float w3 = cW1[(c + 3) * 256 + f1];
#pragma unroll
            for (int s = 0; s < 16; s++) {
                float4 x = *(const float4*)(&sin_[s][c]);
                acc[s] = fmaf(x.x, w0, acc[s]);
                acc[s] = fmaf(x.y, w1, acc[s]);
                acc[s] = fmaf(x.z, w2, acc[s]);
                acc[s] = fmaf(x.w, w3, acc[s]);
            }
        }
#pragma unroll
        for (int s = 0; s < 16; s++) part[h1 * 4096 + s * 256 + f1] = acc[s];
    }
    __syncthreads();
    {   // LN stats over 256 (warp w -> sample w)
        float sum = 0.f, sq = 0.f;
#pragma unroll
        for (int j = 0; j < 8; j++) {
            int f = lane + 32 * j;
            float x = part[w * 256 + f] + part[4096 + w * 256 + f];
            sum += x; sq = fmaf(x, x, sq);
        }
        sum = warpSum(sum); sq = warpSum(sq);
        if (lane == 0) {
            float m = sum * (1.f / 256.f);
            float v = sq * (1.f / 256.f) - m * m;
            sstat[w][0] = m; sstat[w][1] = rsqrtf(v + EPS);
        }
    }
    __syncthreads();
    {   // combine + LN + ReLU -> ACTA
        const float g = cg1[f1], e = cbe1[f1];
#pragma unroll
        for (int i = 0; i < 8; i++) {
            const int s = h1 + 2 * i;
            float x = part[s * 256 + f1] + part[4096 + s * 256 + f1];
            ACTA(s, f1) = fmaxf(fmaf((x - sstat[s][0]) * sstat[s][1], g, e), 0.f);
        }
    }
    __syncthreads();

    // ================= coarse L2 (256 -> 128), c-split (4 quarters) =========
    const int f2q = tid & 127, q2 = tid >> 7;
    {
        float acc[16];
        const float bv = (q2 == 0) ? cb2[f2q] : 0.f;
#pragma unroll
        for (int s = 0; s < 16; s++) acc[s] = bv;
        const int c0 = q2 * 64;
#pragma unroll 2
        for (int cc = 0; cc < 64; cc += 4) {
            const int c = c0 + cc;
            float w0 = cW2[(c + 0) * 128 + f2q];
            float w1 = cW2[(c + 1) * 128 + f2q];
            float w2 = cW2[(c + 2) * 128 + f2q];
            float w3 = cW2[(c + 3) * 128 + f2q];
#pragma unroll
            for (int s = 0; s < 16; s++) {
                float4 x = *(const float4*)(&ACTA(s, c));
                acc[s] = fmaf(x.x, w0, acc[s]);
                acc[s] = fmaf(x.y, w1, acc[s]);
                acc[s] = fmaf(x.z, w2, acc[s]);
                acc[s] = fmaf(x.w, w3, acc[s]);
            }
        }
#pragma unroll
        for (int s = 0; s < 16; s++) part[q2 * 2048 + s * 128 + f2q] = acc[s];
    }
    __syncthreads();
    {   // LN stats over 128
        float sum = 0.f, sq = 0.f;
#pragma unroll
        for (int j = 0; j < 4; j++) {
            int f = lane + 32 * j;
            float x = part[w * 128 + f] + part[2048 + w * 128 + f]
                    + part[4096 + w * 128 + f] + part[6144 + w * 128 + f];
            sum += x; sq = fmaf(x, x, sq);
        }
        sum = warpSum(sum); sq = warpSum(sq);
        if (lane == 0) {
            float m = sum * (1.f / 128.f);
            float v = sq * (1.f / 128.f) - m * m;
            sstat[w][0] = m; sstat[w][1] = rsqrtf(v + EPS);
        }
    }
    __syncthreads();
    {   // combine + LN + ReLU -> ACTB
        const float g = cg2[f2q], e = cbe2[f2q];
#pragma unroll
        for (int i = 0; i < 4; i++) {
            const int s = q2 + 4 * i;
            float x = part[s * 128 + f2q] + part[2048 + s * 128 + f2q]
                    + part[4096 + s * 128 + f2q] + part[6144 + s * 128 + f2q];
            ACTB(s, f2q) = fmaxf(fmaf((x - sstat[s][0]) * sstat[s][1], g, e), 0.f);
        }
    }
    __syncthreads();

    // ================= coarse L3 (warp w -> sample w) -> scoarse ============
    {
        float p0 = 0.f, p1 = 0.f, p2 = 0.f;
#pragma unroll
        for (int t = 0; t < 4; t++) {
            int c = lane + 32 * t;
            float x = ACTB(w, c);
            p0 = fmaf(x, cW3[c * 3 + 0], p0);
            p1 = fmaf(x, cW3[c * 3 + 1], p1);
            p2 = fmaf(x, cW3[c * 3 + 2], p2);
        }
        p0 = warpSum(p0) + cb3[0];
        p1 = warpSum(p1) + cb3[1];
        p2 = warpSum(p2) + cb3[2];
        if (lane < 3)
            scoarse[w][lane] = (lane == 0) ? p0 : (lane == 1) ? p1 : p2;
    }
    __syncthreads();

    // ================= refinement: warp w -> sorted sample sslot[w] =========
    const int s = sslot[w];
    const int k = scls[s];
    const int f4 = lane * 4, f2 = lane * 2;

    // refine L1: 96 -> 128
    {
        const float* W = rW1 + k * 96 * 128;
        float4 bb = *(const float4*)(rb1 + k * 128 + f4);
        float B0[4] = {bb.x, bb.y, bb.z, bb.w};
#pragma unroll 2
        for (int c = 0; c < 96; c += 4) {
            float4 x = *(const float4*)(&sin_[s][c]);
            float4 wv;
            wv = *(const float4*)(W + (c + 0) * 128 + f4);
            B0[0] = fmaf(x.x, wv.x, B0[0]); B0[1] = fmaf(x.x, wv.y, B0[1]);
            B0[2] = fmaf(x.x, wv.z, B0[2]); B0[3] = fmaf(x.x, wv.w, B0[3]);
            wv = *(const float4*)(W + (c + 1) * 128 + f4);
            B0[0] = fmaf(x.y, wv.x, B0[0]); B0[1] = fmaf(x.y, wv.y, B0[1]);
            B0[2] = fmaf(x.y, wv.z, B0[2]); B0[3] = fmaf(x.y, wv.w, B0[3]);
            wv = *(const float4*)(W + (c + 2) * 128 + f4);
            B0[0] = fmaf(x.z, wv.x, B0[0]); B0[1] = fmaf(x.z, wv.y, B0[1]);
            B0[2] = fmaf(x.z, wv.z, B0[2]); B0[3] = fmaf(x.z, wv.w, B0[3]);
            wv = *(const float4*)(W + (c + 3) * 128 + f4);
            B0[0] = fmaf(x.w, wv.x, B0[0]); B0[1] = fmaf(x.w, wv.y, B0[1]);
            B0[2] = fmaf(x.w, wv.z, B0[2]); B0[3] = fmaf(x.w, wv.w, B0[3]);
        }
        float m = warpSum(B0[0] + B0[1] + B0[2] + B0[3]) * (1.f / 128.f);
        float v = 0.f;
#pragma unroll
        for (int j = 0; j < 4; j++) { float d = B0[j] - m; v = fmaf(d, d, v); }
        float r = rsqrtf(warpSum(v) * (1.f / 128.f) + EPS);
        float4 g = *(const float4*)(rg1 + k * 128 + f4);
        float4 e = *(const float4*)(rbe1 + k * 128 + f4);
        float4 o;
        o.x = fmaxf(fmaf((B0[0] - m) * r, g.x, e.x), 0.f);
        o.y = fmaxf(fmaf((B0[1] - m) * r, g.y, e.y), 0.f);
        o.z = fmaxf(fmaf((B0[2] - m) * r, g.z, e.z), 0.f);
        o.w = fmaxf(fmaf((B0[3] - m) * r, g.w, e.w), 0.f);
        *(float4*)(&ACTA(s, f4)) = o;
    }
    __syncwarp();

    // refine L2: 128 -> 64
    float r2out0, r2out1;
    {
        const float* W = rW2 + k * 128 * 64;
        float2 bb = *(const float2*)(rb2 + k * 64 + f2);
        float D0[2] = {bb.x, bb.y};
#pragma unroll 2
        for (int c = 0; c < 128; c += 4) {
            float4 x = *(const float4*)(&ACTA(s, c));
            float2 wv;
            wv = *(const float2*)(W + (c + 0) * 64 + f2);
            D0[0] = fmaf(x.x, wv.x, D0[0]); D0[1] = fmaf(x.x, wv.y, D0[1]);
            wv = *(const float2*)(W + (c + 1) * 64 + f2);
            D0[0] = fmaf(x.y, wv.x, D0[0]); D0[1] = fmaf(x.y, wv.y, D0[1]);
            wv = *(const float2*)(W + (c + 2) * 64 + f2);
            D0[0] = fmaf(x.z, wv.x, D0[0]); D0[1] = fmaf(x.z, wv.y, D0[1]);
            wv = *(const float2*)(W + (c + 3) * 64 + f2);
            D0[0] = fmaf(x.w, wv.x, D0[0]); D0[1] = fmaf(x.w, wv.y, D0[1]);
        }
        float m = warpSum(D0[0] + D0[1]) * (1.f / 64.f);
        float d0 = D0[0] - m, d1 = D0[1] - m;
        float r = rsqrtf(warpSum(d0 * d0 + d1 * d1) * (1.f / 64.f) + EPS);
        float2 g = *(const float2*)(rg2 + k * 64 + f2);
        float2 e = *(const float2*)(rbe2 + k * 64 + f2);
        r2out0 = fmaxf(fmaf(d0 * r, g.x, e.x), 0.f);
        r2out1 = fmaxf(fmaf(d1 * r, g.y, e.y), 0.f);
    }
    __syncwarp();

    // refine L3: 64 -> 3 via shuffles, add coarse(s), write out sample s
    {
        const float* W3 = rW3 + k * 192;
        float q0 = r2out0 * W3[f2 * 3 + 0] + r2out1 * W3[(f2 + 1) * 3 + 0];
        float q1 = r2out0 * W3[f2 * 3 + 1] + r2out1 * W3[(f2 + 1) * 3 + 1];
        float q2 = r2out0 * W3[f2 * 3 + 2] + r2out1 * W3[(f2 + 1) * 3 + 2];
        q0 = warpSum(q0) + rb3[k * 3 + 0];
        q1 = warpSum(q1) + rb3[k * 3 + 1];
        q2 = warpSum(q2) + rb3[k * 3 + 2];

        if ((b16 + s) < B && lane < 3) {
            float qc = (lane == 0) ? q0 : (lane == 1) ? q1 : q2;
            out[(b16 + s) * 3 + lane] = scoarse[s][lane] + qc;
        }
    }
    #undef ACTA
    #undef ACTB
}

// ---------------- launch ----------------
extern "C" void kernel_launch(void* const* d_in, const int* in_sizes, int n_in,
                              void* d_out, int out_size) {
    const float* feat = (const float*)d_in[0];
    const int*   seg  = (const int*)d_in[1];
    const int*   cls  = (const int*)d_in[2];
    const int N = in_sizes[1];
    const int B = in_sizes[2];

    const int smem_bytes = SMEM_FLOATS * 4;       // ~78 KB -> 2 CTAs/SM
    cudaFuncSetAttribute(fused_kernel, cudaFuncAttributeMaxDynamicSharedMemorySize,
                         smem_bytes);

    bounds_kernel<<<(N / 4 + 255) / 256, 256>>>(seg, N, B);
    fused_kernel<<<(B + 15) / 16, 512, smem_bytes>>>(
        feat, cls,
        (const float*)d_in[3],  (const float*)d_in[4],  (const float*)d_in[5],  (const float*)d_in[6],
        (const float*)d_in[7],  (const float*)d_in[8],  (const float*)d_in[9],  (const float*)d_in[10],
        (const float*)d_in[11], (const float*)d_in[12],
        (const float*)d_in[13], (const float*)d_in[14], (const float*)d_in[15], (const float*)d_in[16],
        (const float*)d_in[17], (const float*)d_in[18], (const float*)d_in[19], (const float*)d_in[20],
        (const float*)d_in[21], (const float*)d_in[22],
        (float*)d_out, B);
}